// round 1
// baseline (speedup 1.0000x reference)
#include <cuda_runtime.h>
#include <cuda_bf16.h>
#include <cstdint>

// ---------------- problem constants ----------------
#define BATCH 8
#define CCH   64
#define HH    64
#define WW    64
#define NPOS  4096      // H*W
#define LSEQ  77
#define DTXT  512
#define NBLK  16
#define NHEAD 8
#define HDIM  8

// ---------------- device scratch ----------------
__device__ float g_tf  [BATCH*LSEQ*CCH];          // text features [b,l,c]
__device__ float g_kn  [BATCH*LSEQ*CCH];          // LN'd keys
__device__ float g_v   [BATCH*LSEQ*CCH];          // values
__device__ float g_feat[BATCH*CCH*HH*WW];         // feature map [b,c,y,x]
__device__ float g_qn  [BATCH*NPOS*CCH];          // q_norm [b,n,c]
__device__ float g_ao  [BATCH*NPOS*CCH];          // attn out [b,n,c]
__device__ float g_u1  [BATCH*CCH*128*128];       // after up level 0
__device__ float g_u2  [(size_t)BATCH*CCH*256*256]; // after up level 1
__device__ float g_wupT[2*64*9*256];              // transposed up weights [lvl,ic,k,oc4]

// ---------------- text projection ----------------
// tf[b,l,c] = sum_d th[b,l,d]*pw[c,d] + pb[c]
__global__ void k_textproj(const float* __restrict__ th,
                           const float* __restrict__ pw,
                           const float* __restrict__ pb) {
    __shared__ float s[DTXT];
    int bl = blockIdx.x;                  // b*77+l
    const float* row = th + (size_t)bl * DTXT;
    for (int i = threadIdx.x; i < DTXT; i += 64) s[i] = row[i];
    __syncthreads();
    int c = threadIdx.x;
    const float* w = pw + (size_t)c * DTXT;
    float acc = pb[c];
#pragma unroll 8
    for (int d = 0; d < DTXT; ++d) acc += s[d] * w[d];
    g_tf[bl * CCH + c] = acc;
}

// ---------------- input conv 3->64, 3x3 ----------------
__global__ void k_convin(const float* __restrict__ x,
                         const float* __restrict__ w,
                         const float* __restrict__ bias) {
    __shared__ float sw[64 * 27];
    __shared__ float sb[64];
    __shared__ float sin[3][3][66];
    int bid = blockIdx.x; int b = bid >> 6; int y = bid & 63;
    int tid = threadIdx.x;
    for (int i = tid; i < 64 * 27; i += 64) sw[i] = w[i];
    sb[tid] = bias[tid];
    for (int ic = 0; ic < 3; ic++)
        for (int r = 0; r < 3; r++) {
            int yy = y + r - 1;
            float v = 0.f;
            if (yy >= 0 && yy < HH) v = x[(((size_t)b * 3 + ic) * HH + yy) * WW + tid];
            sin[ic][r][tid + 1] = v;
            if (tid == 0) { sin[ic][r][0] = 0.f; sin[ic][r][65] = 0.f; }
        }
    __syncthreads();
    int xx = tid;
    for (int oc = 0; oc < 64; oc++) {
        float acc = sb[oc];
#pragma unroll
        for (int ic = 0; ic < 3; ic++)
#pragma unroll
            for (int r = 0; r < 3; r++)
#pragma unroll
                for (int kx = 0; kx < 3; kx++)
                    acc += sin[ic][r][xx + kx] * sw[(oc * 3 + ic) * 9 + r * 3 + kx];
        g_feat[(((size_t)b * CCH + oc) * HH + y) * WW + xx] = acc;
    }
}

// ---------------- K/V projection + LN(K) ----------------
__global__ void k_kv(const float* __restrict__ kw, const float* __restrict__ kb,
                     const float* __restrict__ vw, const float* __restrict__ vb,
                     const float* __restrict__ l2w, const float* __restrict__ l2b) {
    __shared__ float s[CCH];
    __shared__ float ksm[CCH];
    int bl = blockIdx.x;
    int o = threadIdx.x;
    s[o] = g_tf[bl * CCH + o];
    __syncthreads();
    float ka = kb[o], va = vb[o];
    const float* kr = kw + o * CCH;
    const float* vr = vw + o * CCH;
#pragma unroll
    for (int c = 0; c < CCH; c++) { float t = s[c]; ka += t * kr[c]; va += t * vr[c]; }
    ksm[o] = ka;
    __syncthreads();
    float m = 0.f;
#pragma unroll 8
    for (int i = 0; i < CCH; i++) m += ksm[i];
    m *= (1.f / 64.f);
    float vv = 0.f;
#pragma unroll 8
    for (int i = 0; i < CCH; i++) { float d = ksm[i] - m; vv += d * d; }
    vv *= (1.f / 64.f);
    float rs = rsqrtf(vv + 1e-5f);
    g_kn[bl * CCH + o] = (ka - m) * rs * l2w[o] + l2b[o];
    g_v [bl * CCH + o] = va;
}

// ---------------- Q projection + pos-enc + LN, fused ----------------
// block = (b, y). 256 threads: og = tid&15 (o0=og*4), xg = tid>>4 (x0=xg*4).
__global__ void __launch_bounds__(256) k_qln(
        const float* __restrict__ qw, const float* __restrict__ qb,
        const float* __restrict__ l1w, const float* __restrict__ l1b) {
    __shared__ float ft [64][64];   // [i][x]
    __shared__ float wsT[64][64];   // [i][o]
    int bid = blockIdx.x; int b = bid >> 6; int y = bid & 63;
    int tid = threadIdx.x;
    for (int idx = tid; idx < 4096; idx += 256) {
        int i = idx >> 6, xx = idx & 63;
        ft[i][xx] = g_feat[(((size_t)b * CCH + i) * HH + y) * WW + xx];
    }
    for (int idx = tid; idx < 4096; idx += 256) {
        int o = idx >> 6, i = idx & 63;
        wsT[i][o] = qw[idx];
    }
    __syncthreads();
    int og = tid & 15, xg = tid >> 4;
    int o0 = og * 4, x0 = xg * 4;
    float4 bq = *(const float4*)&qb[o0];
    float acc[4][4];   // [xi][oj]
#pragma unroll
    for (int xi = 0; xi < 4; xi++) {
        acc[xi][0] = bq.x; acc[xi][1] = bq.y; acc[xi][2] = bq.z; acc[xi][3] = bq.w;
    }
#pragma unroll 8
    for (int i = 0; i < 64; i++) {
        float4 fx = *(const float4*)&ft[i][x0];
        float4 wv = *(const float4*)&wsT[i][o0];
        acc[0][0] += fx.x * wv.x; acc[0][1] += fx.x * wv.y; acc[0][2] += fx.x * wv.z; acc[0][3] += fx.x * wv.w;
        acc[1][0] += fx.y * wv.x; acc[1][1] += fx.y * wv.y; acc[1][2] += fx.y * wv.z; acc[1][3] += fx.y * wv.w;
        acc[2][0] += fx.z * wv.x; acc[2][1] += fx.z * wv.y; acc[2][2] += fx.z * wv.z; acc[2][3] += fx.z * wv.w;
        acc[3][0] += fx.w * wv.x; acc[3][1] += fx.w * wv.y; acc[3][2] += fx.w * wv.z; acc[3][3] += fx.w * wv.w;
    }
    // positional encoding: channels [0,32) get x/(W-1), [32,64) get y/(H-1), scaled 0.05
    float pey = (float)y * (0.05f / 63.f);
#pragma unroll
    for (int xi = 0; xi < 4; xi++) {
        float pex = (float)(x0 + xi) * (0.05f / 63.f);
#pragma unroll
        for (int oj = 0; oj < 4; oj++)
            acc[xi][oj] += ((o0 + oj) < 32) ? pex : pey;
    }
    // LayerNorm over channel dim per x: reduce across the 16 og-lanes
    float4 lw = *(const float4*)&l1w[o0];
    float4 lb = *(const float4*)&l1b[o0];
    size_t base = ((size_t)b * NPOS + (size_t)y * 64) * CCH;
#pragma unroll
    for (int xi = 0; xi < 4; xi++) {
        float s = acc[xi][0] + acc[xi][1] + acc[xi][2] + acc[xi][3];
#pragma unroll
        for (int off = 1; off < 16; off <<= 1) s += __shfl_xor_sync(0xffffffffu, s, off);
        float mean = s * (1.f / 64.f);
        float d0 = acc[xi][0] - mean, d1 = acc[xi][1] - mean,
              d2 = acc[xi][2] - mean, d3 = acc[xi][3] - mean;
        float sq = d0 * d0 + d1 * d1 + d2 * d2 + d3 * d3;
#pragma unroll
        for (int off = 1; off < 16; off <<= 1) sq += __shfl_xor_sync(0xffffffffu, sq, off);
        float rs = rsqrtf(sq * (1.f / 64.f) + 1e-5f);
        float4 out;
        out.x = d0 * rs * lw.x + lb.x;
        out.y = d1 * rs * lw.y + lb.y;
        out.z = d2 * rs * lw.z + lb.z;
        out.w = d3 * rs * lw.w + lb.w;
        *(float4*)&g_qn[base + (size_t)(x0 + xi) * CCH + o0] = out;
    }
}

// ---------------- attention ----------------
// block = (b, 32-position chunk); thread = (pos_local, head)
__global__ void __launch_bounds__(256) k_attn() {
    __shared__ __align__(16) float ks[LSEQ * CCH];
    __shared__ __align__(16) float vs[LSEQ * CCH];
    int b = blockIdx.x >> 7, pc = blockIdx.x & 127;
    int tid = threadIdx.x;
    const float* kg = g_kn + (size_t)b * LSEQ * CCH;
    const float* vg = g_v  + (size_t)b * LSEQ * CCH;
    for (int i = tid; i < LSEQ * CCH; i += 256) { ks[i] = kg[i]; vs[i] = vg[i]; }
    __syncthreads();
    int h = tid & 7, pl = tid >> 3;
    int n = pc * 32 + pl;
    const float* qp = g_qn + ((size_t)b * NPOS + n) * CCH + h * HDIM;
    float4 q0 = *(const float4*)qp;
    float4 q1 = *(const float4*)(qp + 4);
    const float scale = 0.35355339059327373f;  // 8^-0.5
    float m = -1e30f, den = 0.f;
    float o0 = 0, o1 = 0, o2 = 0, o3 = 0, o4 = 0, o5 = 0, o6 = 0, o7 = 0;
    for (int l = 0; l < LSEQ; l++) {
        const float4* kp = (const float4*)&ks[l * CCH + h * HDIM];
        float4 k0 = kp[0], k1 = kp[1];
        float lg = q0.x * k0.x + q0.y * k0.y + q0.z * k0.z + q0.w * k0.w
                 + q1.x * k1.x + q1.y * k1.y + q1.z * k1.z + q1.w * k1.w;
        lg *= scale;
        float nm = fmaxf(m, lg);
        float corr = __expf(m - nm);
        float e    = __expf(lg - nm);
        den = den * corr + e;
        const float4* vp = (const float4*)&vs[l * CCH + h * HDIM];
        float4 v0 = vp[0], v1 = vp[1];
        o0 = o0 * corr + e * v0.x; o1 = o1 * corr + e * v0.y;
        o2 = o2 * corr + e * v0.z; o3 = o3 * corr + e * v0.w;
        o4 = o4 * corr + e * v1.x; o5 = o5 * corr + e * v1.y;
        o6 = o6 * corr + e * v1.z; o7 = o7 * corr + e * v1.w;
        m = nm;
    }
    float inv = 1.f / den;
    float* op = g_ao + ((size_t)b * NPOS + n) * CCH + h * HDIM;
    float4 r0 = make_float4(o0 * inv, o1 * inv, o2 * inv, o3 * inv);
    float4 r1 = make_float4(o4 * inv, o5 * inv, o6 * inv, o7 * inv);
    *(float4*)op = r0;
    *(float4*)(op + 4) = r1;
}

// ---------------- output projection + residual ----------------
// block=(b,y). 256 threads: xg = tid&15, og = tid>>4.
__global__ void __launch_bounds__(256) k_outproj(
        const float* __restrict__ ow, const float* __restrict__ ob) {
    __shared__ float at [64][68];   // [i][x], padded for transposed write + f4 align
    __shared__ float wsT[64][64];   // [i][o]
    int bid = blockIdx.x; int b = bid >> 6; int y = bid & 63;
    int tid = threadIdx.x;
    size_t base = ((size_t)b * NPOS + (size_t)y * 64) * CCH;
    for (int idx = tid; idx < 4096; idx += 256) {
        int xx = idx >> 6, i = idx & 63;
        at[i][xx] = g_ao[base + idx];
    }
    for (int idx = tid; idx < 4096; idx += 256) {
        int o = idx >> 6, i = idx & 63;
        wsT[i][o] = ow[idx];
    }
    __syncthreads();
    int xg = tid & 15, og = tid >> 4;
    int x0 = xg * 4, o0 = og * 4;
    float acc[4][4];   // [oj][xi]
#pragma unroll
    for (int oj = 0; oj < 4; oj++)
#pragma unroll
        for (int xi = 0; xi < 4; xi++) acc[oj][xi] = 0.f;
#pragma unroll 8
    for (int i = 0; i < 64; i++) {
        float4 fx = *(const float4*)&at[i][x0];
        float4 wv = *(const float4*)&wsT[i][o0];
        acc[0][0] += wv.x * fx.x; acc[0][1] += wv.x * fx.y; acc[0][2] += wv.x * fx.z; acc[0][3] += wv.x * fx.w;
        acc[1][0] += wv.y * fx.x; acc[1][1] += wv.y * fx.y; acc[1][2] += wv.y * fx.z; acc[1][3] += wv.y * fx.w;
        acc[2][0] += wv.z * fx.x; acc[2][1] += wv.z * fx.y; acc[2][2] += wv.z * fx.z; acc[2][3] += wv.z * fx.w;
        acc[3][0] += wv.w * fx.x; acc[3][1] += wv.w * fx.y; acc[3][2] += wv.w * fx.z; acc[3][3] += wv.w * fx.w;
    }
    float4 bo = *(const float4*)&ob[o0];
    float bov[4] = { bo.x, bo.y, bo.z, bo.w };
#pragma unroll
    for (int oj = 0; oj < 4; oj++) {
        int o = o0 + oj;
        float* fp = &g_feat[(((size_t)b * CCH + o) * HH + y) * WW + x0];
        float4 f = *(float4*)fp;
        f.x += acc[oj][0] + bov[oj];
        f.y += acc[oj][1] + bov[oj];
        f.z += acc[oj][2] + bov[oj];
        f.w += acc[oj][3] + bov[oj];
        *(float4*)fp = f;
    }
}

// ---------------- up-conv weight transpose: [lvl,oc4,ic,k] -> [lvl,ic,k,oc4] ----------------
__global__ void k_wtrans(const float* __restrict__ w) {
    int idx = blockIdx.x * 256 + threadIdx.x;
    if (idx >= 2 * 256 * 64 * 9) return;
    int k  = idx % 9;
    int t  = idx / 9;
    int ic = t % 64; t /= 64;
    int oc4 = t % 256;
    int lvl = t / 256;
    g_wupT[(((lvl * 64 + ic) * 9 + k) * 256) + oc4] = w[idx];
}

// ---------------- up-sample conv (64->256) + pixel-shuffle + relu ----------------
// grid: (IW/16, IH/8, B*4). 256 threads: ocq = tid&7 (8 oc4), pg = tid>>3 -> (tx,ty).
__global__ void __launch_bounds__(256) k_upconv(int lvl, int IH, int IW,
                                                const float* __restrict__ up_b) {
    const float* in  = lvl ? g_u1 : g_feat;
    float*       outp = lvl ? g_u2 : g_u1;
    __shared__ float sin[16][10][18];
    __shared__ float ws [16][9][64];
    int x0 = blockIdx.x * 16, y0 = blockIdx.y * 8;
    int bz = blockIdx.z; int b = bz >> 2; int ocg = bz & 3;
    int tid = threadIdx.x;
    int ocq = tid & 7; int pg = tid >> 3;
    int tx = (pg & 3) * 4; int ty = pg >> 2;
    int ocb = ocg * 64 + ocq * 8;
    float acc[8][4];
#pragma unroll
    for (int j = 0; j < 8; j++) {
        float bb = up_b[lvl * 256 + ocb + j];
#pragma unroll
        for (int xi = 0; xi < 4; xi++) acc[j][xi] = bb;
    }
    for (int ic0 = 0; ic0 < 64; ic0 += 16) {
        __syncthreads();
        for (int idx = tid; idx < 16 * 10 * 18; idx += 256) {
            int c = idx % 18; int r = (idx / 18) % 10; int icc = idx / 180;
            int gy = y0 - 1 + r, gx = x0 - 1 + c;
            float v = 0.f;
            if (gy >= 0 && gy < IH && gx >= 0 && gx < IW)
                v = in[(((size_t)b * 64 + ic0 + icc) * IH + gy) * IW + gx];
            sin[icc][r][c] = v;
        }
        for (int idx = tid; idx < 16 * 9 * 64; idx += 256) {
            int oc = idx & 63; int kk = (idx >> 6) % 9; int icc = idx / 576;
            ws[icc][kk][oc] =
                g_wupT[(((lvl * 64 + ic0 + icc) * 9 + kk) * 256) + ocg * 64 + oc];
        }
        __syncthreads();
        for (int icc = 0; icc < 16; icc++) {
#pragma unroll
            for (int ky = 0; ky < 3; ky++) {
                float in6[6];
#pragma unroll
                for (int t = 0; t < 6; t++) in6[t] = sin[icc][ty + ky][tx + t];
#pragma unroll
                for (int kx = 0; kx < 3; kx++) {
                    float4 wA = *(const float4*)&ws[icc][ky * 3 + kx][ocq * 8];
                    float4 wB = *(const float4*)&ws[icc][ky * 3 + kx][ocq * 8 + 4];
#pragma unroll
                    for (int xi = 0; xi < 4; xi++) {
                        float f = in6[kx + xi];
                        acc[0][xi] += wA.x * f; acc[1][xi] += wA.y * f;
                        acc[2][xi] += wA.z * f; acc[3][xi] += wA.w * f;
                        acc[4][xi] += wB.x * f; acc[5][xi] += wB.y * f;
                        acc[6][xi] += wB.z * f; acc[7][xi] += wB.w * f;
                    }
                }
            }
        }
    }
    int OW = IW * 2;
    int gy = y0 + ty, gxb = x0 + tx;
#pragma unroll
    for (int j = 0; j < 8; j++) {
        int oc4 = ocb + j;
        int c = oc4 >> 2, r1 = (oc4 >> 1) & 1, r2 = oc4 & 1;
        size_t rowbase = (((size_t)b * 64 + c) * (size_t)(IH * 2) + (size_t)(2 * gy + r1)) * (size_t)OW;
#pragma unroll
        for (int xi = 0; xi < 4; xi++)
            outp[rowbase + 2 * (gxb + xi) + r2] = fmaxf(acc[j][xi], 0.f);
    }
}

// ---------------- final conv 64->3 at 256x256 ----------------
// grid: dim3(2 xhalf, 32 ytiles, 8 b). threads 256: xg = tid&31 (x0=xg*4), yr = tid>>5 (0..7)
__global__ void __launch_bounds__(256) k_cl(const float* __restrict__ w,
                                            const float* __restrict__ bias,
                                            float* __restrict__ out) {
    __shared__ float sw[3 * 64 * 9];
    __shared__ float sin[4][10][132];
    int xbase = blockIdx.x * 128;
    int y0 = blockIdx.y * 8;
    int b = blockIdx.z;
    int tid = threadIdx.x;
    int xg = tid & 31; int yr = tid >> 5;
    int x0 = xg * 4;
    for (int i = tid; i < 1728; i += 256) sw[i] = w[i];
    float acc[3][4];
#pragma unroll
    for (int oc = 0; oc < 3; oc++) {
        float bb = bias[oc];
#pragma unroll
        for (int xi = 0; xi < 4; xi++) acc[oc][xi] = bb;
    }
    for (int ic0 = 0; ic0 < 64; ic0 += 4) {
        __syncthreads();
        for (int idx = tid; idx < 4 * 10 * 130; idx += 256) {
            int c = idx % 130; int r = (idx / 130) % 10; int icc = idx / 1300;
            int gy = y0 - 1 + r, gx = xbase - 1 + c;
            float v = 0.f;
            if (gy >= 0 && gy < 256 && gx >= 0 && gx < 256)
                v = g_u2[(((size_t)b * 64 + ic0 + icc) * 256 + gy) * 256 + gx];
            sin[icc][r][c] = v;
        }
        __syncthreads();
        for (int icc = 0; icc < 4; icc++) {
#pragma unroll
            for (int ky = 0; ky < 3; ky++) {
                float in6[6];
#pragma unroll
                for (int t = 0; t < 6; t++) in6[t] = sin[icc][yr + ky][x0 + t];
#pragma unroll
                for (int kx = 0; kx < 3; kx++) {
#pragma unroll
                    for (int oc = 0; oc < 3; oc++) {
                        float wv = sw[(oc * 64 + ic0 + icc) * 9 + ky * 3 + kx];
#pragma unroll
                        for (int xi = 0; xi < 4; xi++)
                            acc[oc][xi] += wv * in6[kx + xi];
                    }
                }
            }
        }
    }
    int gy = y0 + yr, gx0 = xbase + x0;
#pragma unroll
    for (int oc = 0; oc < 3; oc++) {
        float4 v = make_float4(acc[oc][0], acc[oc][1], acc[oc][2], acc[oc][3]);
        *(float4*)&out[(((size_t)b * 3 + oc) * 256 + gy) * 256 + gx0] = v;
    }
}

// ---------------- launcher ----------------
extern "C" void kernel_launch(void* const* d_in, const int* in_sizes, int n_in,
                              void* d_out, int out_size) {
    const float* x      = (const float*)d_in[0];
    const float* th     = (const float*)d_in[1];
    const float* proj_w = (const float*)d_in[2];
    const float* proj_b = (const float*)d_in[3];
    const float* cf_w   = (const float*)d_in[4];
    const float* cf_b   = (const float*)d_in[5];
    const float* qw     = (const float*)d_in[6];
    const float* qb     = (const float*)d_in[7];
    const float* kw     = (const float*)d_in[8];
    const float* kb     = (const float*)d_in[9];
    const float* vw     = (const float*)d_in[10];
    const float* vb     = (const float*)d_in[11];
    const float* ow     = (const float*)d_in[12];
    const float* ob     = (const float*)d_in[13];
    const float* l1w    = (const float*)d_in[14];
    const float* l1b    = (const float*)d_in[15];
    const float* l2w    = (const float*)d_in[16];
    const float* l2b    = (const float*)d_in[17];
    const float* up_w   = (const float*)d_in[18];
    const float* up_b   = (const float*)d_in[19];
    const float* cl_w   = (const float*)d_in[20];
    const float* cl_b   = (const float*)d_in[21];
    float* out = (float*)d_out;

    k_textproj<<<BATCH * LSEQ, 64>>>(th, proj_w, proj_b);
    k_convin<<<BATCH * HH, 64>>>(x, cf_w, cf_b);
    k_wtrans<<<(2 * 256 * 64 * 9 + 255) / 256, 256>>>(up_w);

    for (int blk = 0; blk < NBLK; blk++) {
        k_kv<<<BATCH * LSEQ, 64>>>(kw + blk * 4096, kb + blk * 64,
                                   vw + blk * 4096, vb + blk * 64,
                                   l2w + blk * 64, l2b + blk * 64);
        k_qln<<<BATCH * HH, 256>>>(qw + blk * 4096, qb + blk * 64,
                                   l1w + blk * 64, l1b + blk * 64);
        k_attn<<<BATCH * 128, 256>>>();
        k_outproj<<<BATCH * HH, 256>>>(ow + blk * 4096, ob + blk * 64);
    }

    k_upconv<<<dim3(4, 8, BATCH * 4), 256>>>(0, 64, 64, up_b);
    k_upconv<<<dim3(8, 16, BATCH * 4), 256>>>(1, 128, 128, up_b);
    k_cl<<<dim3(2, 32, BATCH), 256>>>(cl_w, cl_b, out);

    (void)in_sizes; (void)n_in; (void)out_size;
}

// round 2
// speedup vs baseline: 1.1643x; 1.1643x over previous
#include <cuda_runtime.h>
#include <cuda_bf16.h>
#include <cstdint>

// ---------------- problem constants ----------------
#define BATCH 8
#define CCH   64
#define HH    64
#define WW    64
#define NPOS  4096      // H*W
#define LSEQ  77
#define DTXT  512
#define NBLK  16
#define NHEAD 8
#define HDIM  8

// ---------------- device scratch ----------------
__device__ float g_tf  [BATCH*LSEQ*CCH];               // text features [b,l,c]
__device__ float g_kn  [NBLK*BATCH*LSEQ*CCH];          // LN'd keys, all blocks
__device__ float g_v   [NBLK*BATCH*LSEQ*CCH];          // values, all blocks
__device__ float g_feat[BATCH*CCH*HH*WW];              // feature map [b,c,y,x]
__device__ float g_u1  [BATCH*CCH*128*128];            // after up level 0
__device__ float g_u2  [(size_t)BATCH*CCH*256*256];    // after up level 1
__device__ float g_wupT[2*64*9*256];                   // transposed up weights

// ---------------- text projection ----------------
__global__ void k_textproj(const float* __restrict__ th,
                           const float* __restrict__ pw,
                           const float* __restrict__ pb) {
    __shared__ float s[DTXT];
    int bl = blockIdx.x;
    const float* row = th + (size_t)bl * DTXT;
    for (int i = threadIdx.x; i < DTXT; i += 64) s[i] = row[i];
    __syncthreads();
    int c = threadIdx.x;
    const float* w = pw + (size_t)c * DTXT;
    float acc = pb[c];
#pragma unroll 8
    for (int d = 0; d < DTXT; ++d) acc += s[d] * w[d];
    g_tf[bl * CCH + c] = acc;
}

// ---------------- input conv 3->64, 3x3 ----------------
__global__ void k_convin(const float* __restrict__ x,
                         const float* __restrict__ w,
                         const float* __restrict__ bias) {
    __shared__ float sw[64 * 27];
    __shared__ float sb[64];
    __shared__ float sin[3][3][66];
    int bid = blockIdx.x; int b = bid >> 6; int y = bid & 63;
    int tid = threadIdx.x;
    for (int i = tid; i < 64 * 27; i += 64) sw[i] = w[i];
    sb[tid] = bias[tid];
    for (int ic = 0; ic < 3; ic++)
        for (int r = 0; r < 3; r++) {
            int yy = y + r - 1;
            float v = 0.f;
            if (yy >= 0 && yy < HH) v = x[(((size_t)b * 3 + ic) * HH + yy) * WW + tid];
            sin[ic][r][tid + 1] = v;
            if (tid == 0) { sin[ic][r][0] = 0.f; sin[ic][r][65] = 0.f; }
        }
    __syncthreads();
    int xx = tid;
    for (int oc = 0; oc < 64; oc++) {
        float acc = sb[oc];
#pragma unroll
        for (int ic = 0; ic < 3; ic++)
#pragma unroll
            for (int r = 0; r < 3; r++)
#pragma unroll
                for (int kx = 0; kx < 3; kx++)
                    acc += sin[ic][r][xx + kx] * sw[(oc * 3 + ic) * 9 + r * 3 + kx];
        g_feat[(((size_t)b * CCH + oc) * HH + y) * WW + xx] = acc;
    }
}

// ---------------- K/V projection + LN(K), ALL blocks in one launch ----------------
// grid (NBLK, BATCH), 256 threads. o = tid&63, rr = tid>>6 (4 rows/iter).
__global__ void __launch_bounds__(256) k_kvall(
        const float* __restrict__ kw, const float* __restrict__ kb,
        const float* __restrict__ vw, const float* __restrict__ vb,
        const float* __restrict__ l2w, const float* __restrict__ l2b) {
    __shared__ float tfs[LSEQ * 64];
    __shared__ float kws[64 * 68];
    __shared__ float vws[64 * 68];
    __shared__ float ksm[4 * 64];
    int blk = blockIdx.x, b = blockIdx.y;
    int tid = threadIdx.x;
    for (int i = tid; i < LSEQ * 64; i += 256) tfs[i] = g_tf[b * LSEQ * 64 + i];
    for (int idx = tid; idx < 4096; idx += 256) {
        int o = idx >> 6, c = idx & 63;
        kws[c * 68 + o] = kw[blk * 4096 + idx];
        vws[c * 68 + o] = vw[blk * 4096 + idx];
    }
    __syncthreads();
    int o = tid & 63, rr = tid >> 6;
    float kbv = kb[blk * 64 + o], vbv = vb[blk * 64 + o];
    float lwv = l2w[blk * 64 + o], lbv = l2b[blk * 64 + o];
    size_t base = ((size_t)(blk * BATCH + b)) * LSEQ * 64;
    for (int r0 = 0; r0 < 80; r0 += 4) {
        int r = r0 + rr;
        bool act = r < LSEQ;
        float ka = kbv, va = vbv;
        if (act) {
#pragma unroll 8
            for (int c = 0; c < 64; c++) {
                float t = tfs[r * 64 + c];
                ka += t * kws[c * 68 + o];
                va += t * vws[c * 68 + o];
            }
            ksm[rr * 64 + o] = ka;
        }
        __syncthreads();
        if (act) {
            float m = 0.f;
#pragma unroll 8
            for (int i = 0; i < 64; i++) m += ksm[rr * 64 + i];
            m *= (1.f / 64.f);
            float vv = 0.f;
#pragma unroll 8
            for (int i = 0; i < 64; i++) { float d = ksm[rr * 64 + i] - m; vv += d * d; }
            vv *= (1.f / 64.f);
            float rs = rsqrtf(vv + 1e-5f);
            g_kn[base + r * 64 + o] = (ka - m) * rs * lwv + lbv;
            g_v [base + r * 64 + o] = va;
        }
        __syncthreads();
    }
}

// ---------------- FUSED attention stack: all 16 blocks in one launch ----------------
// CTA = (b, y) row. feat row stays in smem across all 16 blocks.
// Phases per block: q-proj+pe+LN -> attention (no-max online softmax) -> out-proj + residual.
__global__ void __launch_bounds__(256, 2) k_attn_stack(
        const float* __restrict__ qw, const float* __restrict__ qb,
        const float* __restrict__ ow, const float* __restrict__ ob,
        const float* __restrict__ l1w, const float* __restrict__ l1b) {
    __shared__ __align__(16) float sK[LSEQ * 64];   // keys  [l][c]
    __shared__ __align__(16) float sV[LSEQ * 64];   // values[l][c]
    __shared__ __align__(16) float sW[64 * 68];     // wT[i][o] (Wq, then Wo)
    __shared__ __align__(16) float sF[64 * 64];     // feat [i][x] (persistent)
    __shared__ __align__(16) float sQ[64 * 68];     // qn [x][c], then aoT [c][x]

    int b = blockIdx.x >> 6, y = blockIdx.x & 63;
    int tid = threadIdx.x;

    // load feat row (once)
    for (int idx = tid; idx < 4096; idx += 256)
        sF[idx] = g_feat[(((size_t)b * 64 + (idx >> 6)) * 64 + y) * 64 + (idx & 63)];

    float pey = (float)y * (0.05f / 63.f);
    const float scale = 0.35355339059327373f;   // 8^-0.5

#pragma unroll 1
    for (int blk = 0; blk < NBLK; blk++) {
        size_t kvbase = ((size_t)(blk * BATCH + b)) * LSEQ * 64;
        __syncthreads();   // prev iter done with sK/sV/sW
        for (int i = tid; i < LSEQ * 64; i += 256) {
            sK[i] = g_kn[kvbase + i];
            sV[i] = g_v [kvbase + i];
        }
        for (int idx = tid; idx < 4096; idx += 256) {
            int o = idx >> 6, i = idx & 63;
            sW[i * 68 + o] = qw[blk * 4096 + idx];
        }
        __syncthreads();

        // ---- phase B: q-proj + pos-enc + LN -> sQ[x][c] ----
        {
            int og = tid & 15, xg = tid >> 4;
            int o0 = og * 4, x0 = xg * 4;
            float4 bq = *(const float4*)&qb[blk * 64 + o0];
            float acc[4][4];
#pragma unroll
            for (int xi = 0; xi < 4; xi++) {
                acc[xi][0] = bq.x; acc[xi][1] = bq.y; acc[xi][2] = bq.z; acc[xi][3] = bq.w;
            }
#pragma unroll 8
            for (int i = 0; i < 64; i++) {
                float4 fx = *(const float4*)&sF[i * 64 + x0];
                float4 wv = *(const float4*)&sW[i * 68 + o0];
                acc[0][0] += fx.x * wv.x; acc[0][1] += fx.x * wv.y; acc[0][2] += fx.x * wv.z; acc[0][3] += fx.x * wv.w;
                acc[1][0] += fx.y * wv.x; acc[1][1] += fx.y * wv.y; acc[1][2] += fx.y * wv.z; acc[1][3] += fx.y * wv.w;
                acc[2][0] += fx.z * wv.x; acc[2][1] += fx.z * wv.y; acc[2][2] += fx.z * wv.z; acc[2][3] += fx.z * wv.w;
                acc[3][0] += fx.w * wv.x; acc[3][1] += fx.w * wv.y; acc[3][2] += fx.w * wv.z; acc[3][3] += fx.w * wv.w;
            }
            float4 lw = *(const float4*)&l1w[blk * 64 + o0];
            float4 lb = *(const float4*)&l1b[blk * 64 + o0];
#pragma unroll
            for (int xi = 0; xi < 4; xi++) {
                float pex = (float)(x0 + xi) * (0.05f / 63.f);
#pragma unroll
                for (int oj = 0; oj < 4; oj++)
                    acc[xi][oj] += ((o0 + oj) < 32) ? pex : pey;
                float s = acc[xi][0] + acc[xi][1] + acc[xi][2] + acc[xi][3];
#pragma unroll
                for (int off = 1; off < 16; off <<= 1) s += __shfl_xor_sync(0xffffffffu, s, off);
                float mean = s * (1.f / 64.f);
                float d0 = acc[xi][0] - mean, d1 = acc[xi][1] - mean,
                      d2 = acc[xi][2] - mean, d3 = acc[xi][3] - mean;
                float sq = d0 * d0 + d1 * d1 + d2 * d2 + d3 * d3;
#pragma unroll
                for (int off = 1; off < 16; off <<= 1) sq += __shfl_xor_sync(0xffffffffu, sq, off);
                float rs = rsqrtf(sq * (1.f / 64.f) + 1e-5f);
                float4 outv;
                outv.x = d0 * rs * lw.x + lb.x;
                outv.y = d1 * rs * lw.y + lb.y;
                outv.z = d2 * rs * lw.z + lb.z;
                outv.w = d3 * rs * lw.w + lb.w;
                *(float4*)&sQ[(x0 + xi) * 68 + o0] = outv;
            }
        }
        __syncthreads();

        // ---- phase C: attention. thread = (pos, head-pair) ----
        {
            int hp = tid & 3, pl = tid >> 2;
            int co = hp * 16;  // channel offset: heads 2hp, 2hp+1
            const float4* qp = (const float4*)&sQ[pl * 68 + co];
            float4 qa0 = qp[0], qa1 = qp[1], qb0 = qp[2], qb1 = qp[3];
            __syncthreads();   // all q reads done before aoT overwrites sQ
            float denA = 0.f, denB = 0.f;
            float4 a0 = make_float4(0, 0, 0, 0), a1 = a0, b0 = a0, b1 = a0;
            for (int l = 0; l < LSEQ; l++) {
                const float4* kp = (const float4*)&sK[l * 64 + co];
                float4 k0 = kp[0], k1 = kp[1], k2 = kp[2], k3 = kp[3];
                float lgA = qa0.x * k0.x + qa0.y * k0.y + qa0.z * k0.z + qa0.w * k0.w
                          + qa1.x * k1.x + qa1.y * k1.y + qa1.z * k1.z + qa1.w * k1.w;
                float lgB = qb0.x * k2.x + qb0.y * k2.y + qb0.z * k2.z + qb0.w * k2.w
                          + qb1.x * k3.x + qb1.y * k3.y + qb1.z * k3.z + qb1.w * k3.w;
                float eA = __expf(lgA * scale);
                float eB = __expf(lgB * scale);
                denA += eA; denB += eB;
                const float4* vp = (const float4*)&sV[l * 64 + co];
                float4 v0 = vp[0], v1 = vp[1], v2 = vp[2], v3 = vp[3];
                a0.x += eA * v0.x; a0.y += eA * v0.y; a0.z += eA * v0.z; a0.w += eA * v0.w;
                a1.x += eA * v1.x; a1.y += eA * v1.y; a1.z += eA * v1.z; a1.w += eA * v1.w;
                b0.x += eB * v2.x; b0.y += eB * v2.y; b0.z += eB * v2.z; b0.w += eB * v2.w;
                b1.x += eB * v3.x; b1.y += eB * v3.y; b1.z += eB * v3.z; b1.w += eB * v3.w;
            }
            float iA = 1.f / denA, iB = 1.f / denB;
            // write transposed: aoT[c][pos]
            sQ[(co + 0) * 68 + pl] = a0.x * iA;  sQ[(co + 1) * 68 + pl] = a0.y * iA;
            sQ[(co + 2) * 68 + pl] = a0.z * iA;  sQ[(co + 3) * 68 + pl] = a0.w * iA;
            sQ[(co + 4) * 68 + pl] = a1.x * iA;  sQ[(co + 5) * 68 + pl] = a1.y * iA;
            sQ[(co + 6) * 68 + pl] = a1.z * iA;  sQ[(co + 7) * 68 + pl] = a1.w * iA;
            sQ[(co + 8) * 68 + pl] = b0.x * iB;  sQ[(co + 9) * 68 + pl] = b0.y * iB;
            sQ[(co + 10) * 68 + pl] = b0.z * iB; sQ[(co + 11) * 68 + pl] = b0.w * iB;
            sQ[(co + 12) * 68 + pl] = b1.x * iB; sQ[(co + 13) * 68 + pl] = b1.y * iB;
            sQ[(co + 14) * 68 + pl] = b1.z * iB; sQ[(co + 15) * 68 + pl] = b1.w * iB;
        }
        __syncthreads();

        // ---- phase D: load Wo transposed ----
        for (int idx = tid; idx < 4096; idx += 256) {
            int o = idx >> 6, i = idx & 63;
            sW[i * 68 + o] = ow[blk * 4096 + idx];
        }
        __syncthreads();

        // ---- phase E: out-proj + residual, update sF in place ----
        {
            int xg = tid & 15, og = tid >> 4;
            int x0 = xg * 4, o0 = og * 4;
            float acc[4][4];   // [oj][xi]
#pragma unroll
            for (int oj = 0; oj < 4; oj++)
#pragma unroll
                for (int xi = 0; xi < 4; xi++) acc[oj][xi] = 0.f;
#pragma unroll 8
            for (int i = 0; i < 64; i++) {
                float4 fx = *(const float4*)&sQ[i * 68 + x0];
                float4 wv = *(const float4*)&sW[i * 68 + o0];
                acc[0][0] += wv.x * fx.x; acc[0][1] += wv.x * fx.y; acc[0][2] += wv.x * fx.z; acc[0][3] += wv.x * fx.w;
                acc[1][0] += wv.y * fx.x; acc[1][1] += wv.y * fx.y; acc[1][2] += wv.y * fx.z; acc[1][3] += wv.y * fx.w;
                acc[2][0] += wv.z * fx.x; acc[2][1] += wv.z * fx.y; acc[2][2] += wv.z * fx.z; acc[2][3] += wv.z * fx.w;
                acc[3][0] += wv.w * fx.x; acc[3][1] += wv.w * fx.y; acc[3][2] += wv.w * fx.z; acc[3][3] += wv.w * fx.w;
            }
            float4 bo = *(const float4*)&ob[blk * 64 + o0];
            float bov[4] = { bo.x, bo.y, bo.z, bo.w };
            __syncthreads();   // all sQ/sW reads done (sF writes don't conflict but keep order)
#pragma unroll
            for (int oj = 0; oj < 4; oj++) {
                float* fp = &sF[(o0 + oj) * 64 + x0];
                float4 f = *(float4*)fp;
                f.x += acc[oj][0] + bov[oj];
                f.y += acc[oj][1] + bov[oj];
                f.z += acc[oj][2] + bov[oj];
                f.w += acc[oj][3] + bov[oj];
                *(float4*)fp = f;
            }
        }
    }
    __syncthreads();
    // write final feat row back (once)
    for (int idx = tid; idx < 4096; idx += 256)
        g_feat[(((size_t)b * 64 + (idx >> 6)) * 64 + y) * 64 + (idx & 63)] = sF[idx];
}

// ---------------- up-conv weight transpose ----------------
__global__ void k_wtrans(const float* __restrict__ w) {
    int idx = blockIdx.x * 256 + threadIdx.x;
    if (idx >= 2 * 256 * 64 * 9) return;
    int k  = idx % 9;
    int t  = idx / 9;
    int ic = t % 64; t /= 64;
    int oc4 = t % 256;
    int lvl = t / 256;
    g_wupT[(((lvl * 64 + ic) * 9 + k) * 256) + oc4] = w[idx];
}

// ---------------- up-sample conv (64->256) + pixel-shuffle + relu ----------------
__global__ void __launch_bounds__(256) k_upconv(int lvl, int IH, int IW,
                                                const float* __restrict__ up_b) {
    const float* in  = lvl ? g_u1 : g_feat;
    float*       outp = lvl ? g_u2 : g_u1;
    __shared__ float sin[16][10][18];
    __shared__ float ws [16][9][64];
    int x0 = blockIdx.x * 16, y0 = blockIdx.y * 8;
    int bz = blockIdx.z; int b = bz >> 2; int ocg = bz & 3;
    int tid = threadIdx.x;
    int ocq = tid & 7; int pg = tid >> 3;
    int tx = (pg & 3) * 4; int ty = pg >> 2;
    int ocb = ocg * 64 + ocq * 8;
    float acc[8][4];
#pragma unroll
    for (int j = 0; j < 8; j++) {
        float bb = up_b[lvl * 256 + ocb + j];
#pragma unroll
        for (int xi = 0; xi < 4; xi++) acc[j][xi] = bb;
    }
    for (int ic0 = 0; ic0 < 64; ic0 += 16) {
        __syncthreads();
        for (int idx = tid; idx < 16 * 10 * 18; idx += 256) {
            int c = idx % 18; int r = (idx / 18) % 10; int icc = idx / 180;
            int gy = y0 - 1 + r, gx = x0 - 1 + c;
            float v = 0.f;
            if (gy >= 0 && gy < IH && gx >= 0 && gx < IW)
                v = in[(((size_t)b * 64 + ic0 + icc) * IH + gy) * IW + gx];
            sin[icc][r][c] = v;
        }
        for (int idx = tid; idx < 16 * 9 * 64; idx += 256) {
            int oc = idx & 63; int kk = (idx >> 6) % 9; int icc = idx / 576;
            ws[icc][kk][oc] =
                g_wupT[(((lvl * 64 + ic0 + icc) * 9 + kk) * 256) + ocg * 64 + oc];
        }
        __syncthreads();
        for (int icc = 0; icc < 16; icc++) {
#pragma unroll
            for (int ky = 0; ky < 3; ky++) {
                float in6[6];
#pragma unroll
                for (int t = 0; t < 6; t++) in6[t] = sin[icc][ty + ky][tx + t];
#pragma unroll
                for (int kx = 0; kx < 3; kx++) {
                    float4 wA = *(const float4*)&ws[icc][ky * 3 + kx][ocq * 8];
                    float4 wB = *(const float4*)&ws[icc][ky * 3 + kx][ocq * 8 + 4];
#pragma unroll
                    for (int xi = 0; xi < 4; xi++) {
                        float f = in6[kx + xi];
                        acc[0][xi] += wA.x * f; acc[1][xi] += wA.y * f;
                        acc[2][xi] += wA.z * f; acc[3][xi] += wA.w * f;
                        acc[4][xi] += wB.x * f; acc[5][xi] += wB.y * f;
                        acc[6][xi] += wB.z * f; acc[7][xi] += wB.w * f;
                    }
                }
            }
        }
    }
    int OW = IW * 2;
    int gy = y0 + ty, gxb = x0 + tx;
#pragma unroll
    for (int j = 0; j < 8; j++) {
        int oc4 = ocb + j;
        int c = oc4 >> 2, r1 = (oc4 >> 1) & 1, r2 = oc4 & 1;
        size_t rowbase = (((size_t)b * 64 + c) * (size_t)(IH * 2) + (size_t)(2 * gy + r1)) * (size_t)OW;
#pragma unroll
        for (int xi = 0; xi < 4; xi++)
            outp[rowbase + 2 * (gxb + xi) + r2] = fmaxf(acc[j][xi], 0.f);
    }
}

// ---------------- final conv 64->3 at 256x256 ----------------
__global__ void __launch_bounds__(256) k_cl(const float* __restrict__ w,
                                            const float* __restrict__ bias,
                                            float* __restrict__ out) {
    __shared__ float sw[3 * 64 * 9];
    __shared__ float sin[4][10][132];
    int xbase = blockIdx.x * 128;
    int y0 = blockIdx.y * 8;
    int b = blockIdx.z;
    int tid = threadIdx.x;
    int xg = tid & 31; int yr = tid >> 5;
    int x0 = xg * 4;
    for (int i = tid; i < 1728; i += 256) sw[i] = w[i];
    float acc[3][4];
#pragma unroll
    for (int oc = 0; oc < 3; oc++) {
        float bb = bias[oc];
#pragma unroll
        for (int xi = 0; xi < 4; xi++) acc[oc][xi] = bb;
    }
    for (int ic0 = 0; ic0 < 64; ic0 += 4) {
        __syncthreads();
        for (int idx = tid; idx < 4 * 10 * 130; idx += 256) {
            int c = idx % 130; int r = (idx / 130) % 10; int icc = idx / 1300;
            int gy = y0 - 1 + r, gx = xbase - 1 + c;
            float v = 0.f;
            if (gy >= 0 && gy < 256 && gx >= 0 && gx < 256)
                v = g_u2[(((size_t)b * 64 + ic0 + icc) * 256 + gy) * 256 + gx];
            sin[icc][r][c] = v;
        }
        __syncthreads();
        for (int icc = 0; icc < 4; icc++) {
#pragma unroll
            for (int ky = 0; ky < 3; ky++) {
                float in6[6];
#pragma unroll
                for (int t = 0; t < 6; t++) in6[t] = sin[icc][yr + ky][x0 + t];
#pragma unroll
                for (int kx = 0; kx < 3; kx++) {
#pragma unroll
                    for (int oc = 0; oc < 3; oc++) {
                        float wv = sw[(oc * 64 + ic0 + icc) * 9 + ky * 3 + kx];
#pragma unroll
                        for (int xi = 0; xi < 4; xi++)
                            acc[oc][xi] += wv * in6[kx + xi];
                    }
                }
            }
        }
    }
    int gy = y0 + yr, gx0 = xbase + x0;
#pragma unroll
    for (int oc = 0; oc < 3; oc++) {
        float4 v = make_float4(acc[oc][0], acc[oc][1], acc[oc][2], acc[oc][3]);
        *(float4*)&out[(((size_t)b * 3 + oc) * 256 + gy) * 256 + gx0] = v;
    }
}

// ---------------- launcher ----------------
extern "C" void kernel_launch(void* const* d_in, const int* in_sizes, int n_in,
                              void* d_out, int out_size) {
    const float* x      = (const float*)d_in[0];
    const float* th     = (const float*)d_in[1];
    const float* proj_w = (const float*)d_in[2];
    const float* proj_b = (const float*)d_in[3];
    const float* cf_w   = (const float*)d_in[4];
    const float* cf_b   = (const float*)d_in[5];
    const float* qw     = (const float*)d_in[6];
    const float* qb     = (const float*)d_in[7];
    const float* kw     = (const float*)d_in[8];
    const float* kb     = (const float*)d_in[9];
    const float* vw     = (const float*)d_in[10];
    const float* vb     = (const float*)d_in[11];
    const float* ow     = (const float*)d_in[12];
    const float* ob     = (const float*)d_in[13];
    const float* l1w    = (const float*)d_in[14];
    const float* l1b    = (const float*)d_in[15];
    const float* l2w    = (const float*)d_in[16];
    const float* l2b    = (const float*)d_in[17];
    const float* up_w   = (const float*)d_in[18];
    const float* up_b   = (const float*)d_in[19];
    const float* cl_w   = (const float*)d_in[20];
    const float* cl_b   = (const float*)d_in[21];
    float* out = (float*)d_out;

    k_textproj<<<BATCH * LSEQ, 64>>>(th, proj_w, proj_b);
    k_convin<<<BATCH * HH, 64>>>(x, cf_w, cf_b);
    k_wtrans<<<(2 * 256 * 64 * 9 + 255) / 256, 256>>>(up_w);
    k_kvall<<<dim3(NBLK, BATCH), 256>>>(kw, kb, vw, vb, l2w, l2b);
    k_attn_stack<<<BATCH * HH, 256>>>(qw, qb, ow, ob, l1w, l1b);

    k_upconv<<<dim3(4, 8, BATCH * 4), 256>>>(0, 64, 64, up_b);
    k_upconv<<<dim3(8, 16, BATCH * 4), 256>>>(1, 128, 128, up_b);
    k_cl<<<dim3(2, 32, BATCH), 256>>>(cl_w, cl_b, out);

    (void)in_sizes; (void)n_in; (void)out_size;
}